// round 1
// baseline (speedup 1.0000x reference)
#include <cuda_runtime.h>
#include <cstddef>

#define EPSV 1e-5f

// problem dims (fixed)
#define NB 2
#define NC 64
#define NT 2048
#define NF 64
#define NH 4
#define NHC 4
#define NVC 16
#define DQK 256   // NHC*NF
#define DV  1024  // NVC*NF
#define NHB 8     // NH*NB

// ---------------- scratch (device globals; no allocations allowed) ----------
__device__ float g_Q[(size_t)NHB * NT * DQK];   // 16 MB
__device__ float g_K[(size_t)NHB * NT * DQK];   // 16 MB
__device__ float g_V[(size_t)NHB * NT * DV];    // 64 MB
__device__ float g_S[(size_t)NHB * NT * NT];    // 128 MB
__device__ float g_O[(size_t)NHB * NT * DV];    // 64 MB

// ---------------- kernel 1: QKV projection + PReLU + per-head LN ------------
// grid (NT/4, NB), block (64, 4): thread = (f, local t)
__global__ __launch_bounds__(256) void qkv_kernel(
    const float* __restrict__ x,
    const float* __restrict__ Wq, const float* __restrict__ bq, const float* __restrict__ aq,
    const float* __restrict__ gq, const float* __restrict__ betaq,
    const float* __restrict__ Wk, const float* __restrict__ bk, const float* __restrict__ ak,
    const float* __restrict__ gk, const float* __restrict__ betak,
    const float* __restrict__ Wv, const float* __restrict__ bv, const float* __restrict__ av,
    const float* __restrict__ gv, const float* __restrict__ betav)
{
    __shared__ float sWq[NH * NHC * NC];
    __shared__ float sWk[NH * NHC * NC];
    __shared__ float sWv[NH * NVC * NC];

    int tid = threadIdx.y * 64 + threadIdx.x;
    for (int i = tid; i < NH * NHC * NC; i += 256) { sWq[i] = Wq[i]; sWk[i] = Wk[i]; }
    for (int i = tid; i < NH * NVC * NC; i += 256) { sWv[i] = Wv[i]; }
    __syncthreads();

    int f = threadIdx.x;
    int t = blockIdx.x * 4 + threadIdx.y;
    int b = blockIdx.y;

    const float* xp = x + ((size_t)b * NC * NT + t) * NF + f;  // step per c: NT*NF

    for (int h = 0; h < NH; h++) {
        float q[NHC], k[NHC], v[NVC];
#pragma unroll
        for (int j = 0; j < NHC; j++) { q[j] = 0.f; k[j] = 0.f; }
#pragma unroll
        for (int j = 0; j < NVC; j++) v[j] = 0.f;

        for (int c0 = 0; c0 < NC; c0 += 4) {
            float xc0 = xp[(size_t)(c0 + 0) * NT * NF];
            float xc1 = xp[(size_t)(c0 + 1) * NT * NF];
            float xc2 = xp[(size_t)(c0 + 2) * NT * NF];
            float xc3 = xp[(size_t)(c0 + 3) * NT * NF];
#pragma unroll
            for (int j = 0; j < NHC; j++) {
                float4 w = *(const float4*)&sWq[(h * NHC + j) * NC + c0];
                q[j] += w.x * xc0 + w.y * xc1 + w.z * xc2 + w.w * xc3;
            }
#pragma unroll
            for (int j = 0; j < NHC; j++) {
                float4 w = *(const float4*)&sWk[(h * NHC + j) * NC + c0];
                k[j] += w.x * xc0 + w.y * xc1 + w.z * xc2 + w.w * xc3;
            }
#pragma unroll
            for (int j = 0; j < NVC; j++) {
                float4 w = *(const float4*)&sWv[(h * NVC + j) * NC + c0];
                v[j] += w.x * xc0 + w.y * xc1 + w.z * xc2 + w.w * xc3;
            }
        }

        // ---- Q: bias, PReLU, LN over NHC, write ----
        {
            float a = aq[h];
            float mu = 0.f;
#pragma unroll
            for (int j = 0; j < NHC; j++) {
                float y = q[j] + bq[h * NHC + j];
                y = (y >= 0.f) ? y : a * y;
                q[j] = y; mu += y;
            }
            mu *= (1.f / NHC);
            float var = 0.f;
#pragma unroll
            for (int j = 0; j < NHC; j++) { float d = q[j] - mu; var += d * d; }
            var *= (1.f / NHC);
            float r = rsqrtf(var + EPSV);
#pragma unroll
            for (int j = 0; j < NHC; j++) {
                float o = (q[j] - mu) * r * gq[h * NHC + j] + betaq[h * NHC + j];
                g_Q[((size_t)(h * NB + b) * NT + t) * DQK + j * NF + f] = o;
            }
        }
        // ---- K ----
        {
            float a = ak[h];
            float mu = 0.f;
#pragma unroll
            for (int j = 0; j < NHC; j++) {
                float y = k[j] + bk[h * NHC + j];
                y = (y >= 0.f) ? y : a * y;
                k[j] = y; mu += y;
            }
            mu *= (1.f / NHC);
            float var = 0.f;
#pragma unroll
            for (int j = 0; j < NHC; j++) { float d = k[j] - mu; var += d * d; }
            var *= (1.f / NHC);
            float r = rsqrtf(var + EPSV);
#pragma unroll
            for (int j = 0; j < NHC; j++) {
                float o = (k[j] - mu) * r * gk[h * NHC + j] + betak[h * NHC + j];
                g_K[((size_t)(h * NB + b) * NT + t) * DQK + j * NF + f] = o;
            }
        }
        // ---- V: LN over NVC ----
        {
            float a = av[h];
            float mu = 0.f;
#pragma unroll
            for (int j = 0; j < NVC; j++) {
                float y = v[j] + bv[h * NVC + j];
                y = (y >= 0.f) ? y : a * y;
                v[j] = y; mu += y;
            }
            mu *= (1.f / NVC);
            float var = 0.f;
#pragma unroll
            for (int j = 0; j < NVC; j++) { float d = v[j] - mu; var += d * d; }
            var *= (1.f / NVC);
            float r = rsqrtf(var + EPSV);
#pragma unroll
            for (int j = 0; j < NVC; j++) {
                float o = (v[j] - mu) * r * gv[h * NVC + j] + betav[h * NVC + j];
                g_V[((size_t)(h * NB + b) * NT + t) * DV + j * NF + f] = o;
            }
        }
    }
}

// ---------------- kernel 2: batched SGEMM, C = alpha * A * B^T ---------------
// A: [M,K] row-major, B: [N,K] row-major, C: [M,N]. 128x128 tile, BK=16.
__global__ __launch_bounds__(256) void sgemm_nt(
    const float* __restrict__ A, const float* __restrict__ Bm, float* __restrict__ C,
    int M, int N, int K, float alpha,
    size_t sA, size_t sB, size_t sC)
{
    A  += (size_t)blockIdx.z * sA;
    Bm += (size_t)blockIdx.z * sB;
    C  += (size_t)blockIdx.z * sC;

    __shared__ float As[16][132];
    __shared__ float Bs[16][132];

    int tid = threadIdx.x;
    int bm = blockIdx.y * 128, bn = blockIdx.x * 128;
    int tm = (tid >> 4) * 8, tn = (tid & 15) * 8;

    float acc[8][8];
#pragma unroll
    for (int i = 0; i < 8; i++)
#pragma unroll
        for (int j = 0; j < 8; j++) acc[i][j] = 0.f;

    for (int k0 = 0; k0 < K; k0 += 16) {
#pragma unroll
        for (int i = 0; i < 2; i++) {
            int idx = tid + i * 256;
            int row = idx >> 2;
            int kc = (idx & 3) << 2;
            float4 va = *(const float4*)(A + (size_t)(bm + row) * K + k0 + kc);
            As[kc + 0][row] = va.x; As[kc + 1][row] = va.y;
            As[kc + 2][row] = va.z; As[kc + 3][row] = va.w;
            float4 vb = *(const float4*)(Bm + (size_t)(bn + row) * K + k0 + kc);
            Bs[kc + 0][row] = vb.x; Bs[kc + 1][row] = vb.y;
            Bs[kc + 2][row] = vb.z; Bs[kc + 3][row] = vb.w;
        }
        __syncthreads();
#pragma unroll
        for (int k = 0; k < 16; k++) {
            float a[8], bb[8];
#pragma unroll
            for (int j = 0; j < 8; j++) a[j] = As[k][tm + j];
#pragma unroll
            for (int j = 0; j < 8; j++) bb[j] = Bs[k][tn + j];
#pragma unroll
            for (int i = 0; i < 8; i++)
#pragma unroll
                for (int j = 0; j < 8; j++) acc[i][j] = fmaf(a[i], bb[j], acc[i][j]);
        }
        __syncthreads();
    }
#pragma unroll
    for (int i = 0; i < 8; i++) {
        float4 r0 = make_float4(alpha * acc[i][0], alpha * acc[i][1],
                                alpha * acc[i][2], alpha * acc[i][3]);
        float4 r1 = make_float4(alpha * acc[i][4], alpha * acc[i][5],
                                alpha * acc[i][6], alpha * acc[i][7]);
        *(float4*)(C + (size_t)(bm + tm + i) * N + bn + tn)     = r0;
        *(float4*)(C + (size_t)(bm + tm + i) * N + bn + tn + 4) = r1;
    }
}

// ---------------- kernel 3: batched SGEMM, C = A * B (NN) --------------------
// A: [M,K] row-major, B: [K,N] row-major, C: [M,N].
__global__ __launch_bounds__(256) void sgemm_nn(
    const float* __restrict__ A, const float* __restrict__ Bm, float* __restrict__ C,
    int M, int N, int K,
    size_t sA, size_t sB, size_t sC)
{
    A  += (size_t)blockIdx.z * sA;
    Bm += (size_t)blockIdx.z * sB;
    C  += (size_t)blockIdx.z * sC;

    __shared__ float As[16][132];
    __shared__ float Bs[16][132];

    int tid = threadIdx.x;
    int bm = blockIdx.y * 128, bn = blockIdx.x * 128;
    int tm = (tid >> 4) * 8, tn = (tid & 15) * 8;

    float acc[8][8];
#pragma unroll
    for (int i = 0; i < 8; i++)
#pragma unroll
        for (int j = 0; j < 8; j++) acc[i][j] = 0.f;

    for (int k0 = 0; k0 < K; k0 += 16) {
#pragma unroll
        for (int i = 0; i < 2; i++) {
            int idx = tid + i * 256;
            // A tile: 128 rows x 16 k
            int row = idx >> 2;
            int kc = (idx & 3) << 2;
            float4 va = *(const float4*)(A + (size_t)(bm + row) * K + k0 + kc);
            As[kc + 0][row] = va.x; As[kc + 1][row] = va.y;
            As[kc + 2][row] = va.z; As[kc + 3][row] = va.w;
            // B tile: 16 k x 128 n (contiguous along n)
            int krow = idx >> 5;
            int nc = (idx & 31) << 2;
            float4 vb = *(const float4*)(Bm + (size_t)(k0 + krow) * N + bn + nc);
            *(float4*)&Bs[krow][nc] = vb;
        }
        __syncthreads();
#pragma unroll
        for (int k = 0; k < 16; k++) {
            float a[8], bb[8];
#pragma unroll
            for (int j = 0; j < 8; j++) a[j] = As[k][tm + j];
#pragma unroll
            for (int j = 0; j < 8; j++) bb[j] = Bs[k][tn + j];
#pragma unroll
            for (int i = 0; i < 8; i++)
#pragma unroll
                for (int j = 0; j < 8; j++) acc[i][j] = fmaf(a[i], bb[j], acc[i][j]);
        }
        __syncthreads();
    }
#pragma unroll
    for (int i = 0; i < 8; i++) {
        float4 r0 = make_float4(acc[i][0], acc[i][1], acc[i][2], acc[i][3]);
        float4 r1 = make_float4(acc[i][4], acc[i][5], acc[i][6], acc[i][7]);
        *(float4*)(C + (size_t)(bm + tm + i) * N + bn + tn)     = r0;
        *(float4*)(C + (size_t)(bm + tm + i) * N + bn + tn + 4) = r1;
    }
}

// ---------------- kernel 4: row softmax over S (rows of length NT) ----------
__global__ __launch_bounds__(256) void softmax_kernel(float* __restrict__ S)
{
    __shared__ float red[256];
    float* p = S + (size_t)blockIdx.x * NT;
    int tid = threadIdx.x;

    float v[8];
    float m = -1e30f;
#pragma unroll
    for (int i = 0; i < 8; i++) { v[i] = p[tid + i * 256]; m = fmaxf(m, v[i]); }
    red[tid] = m; __syncthreads();
#pragma unroll
    for (int s = 128; s > 0; s >>= 1) {
        if (tid < s) red[tid] = fmaxf(red[tid], red[tid + s]);
        __syncthreads();
    }
    m = red[0];
    __syncthreads();

    float sum = 0.f;
#pragma unroll
    for (int i = 0; i < 8; i++) { v[i] = __expf(v[i] - m); sum += v[i]; }
    red[tid] = sum; __syncthreads();
#pragma unroll
    for (int s = 128; s > 0; s >>= 1) {
        if (tid < s) red[tid] += red[tid + s];
        __syncthreads();
    }
    float inv = 1.f / red[0];
#pragma unroll
    for (int i = 0; i < 8; i++) p[tid + i * 256] = v[i] * inv;
}

// ---------------- kernel 5: output projection + PReLU + LN + residual -------
// grid (NT/4, NB), block (64,4)
__global__ __launch_bounds__(256) void out_kernel(
    const float* __restrict__ x,
    const float* __restrict__ Wp, const float* __restrict__ bp, const float* __restrict__ ap,
    const float* __restrict__ gp, const float* __restrict__ betap,
    float* __restrict__ out)
{
    __shared__ float sW[NC * NC];
    int tid = threadIdx.y * 64 + threadIdx.x;
    for (int i = tid; i < NC * NC; i += 256) sW[i] = Wp[i];
    __syncthreads();

    int f = threadIdx.x;
    int t = blockIdx.x * 4 + threadIdx.y;
    int b = blockIdx.y;

    float Og[NC];
#pragma unroll
    for (int c = 0; c < NC; c++) {
        int h = c >> 4, vc = c & 15;  // channel order: c = h*NVC + vc
        Og[c] = g_O[((size_t)(h * NB + b) * NT + t) * DV + vc * NF + f];
    }

    float a = ap[0];
    float yv[NC];
    float s1 = 0.f, s2 = 0.f;
    for (int o = 0; o < NC; o++) {
        float acc = bp[o];
#pragma unroll
        for (int c0 = 0; c0 < NC; c0 += 4) {
            float4 w = *(const float4*)&sW[o * NC + c0];
            acc += w.x * Og[c0] + w.y * Og[c0 + 1] + w.z * Og[c0 + 2] + w.w * Og[c0 + 3];
        }
        acc = (acc >= 0.f) ? acc : a * acc;
        yv[o] = acc;
        s1 += acc; s2 += acc * acc;
    }
    float mu = s1 * (1.f / NC);
    float var = s2 * (1.f / NC) - mu * mu;
    float r = rsqrtf(var + EPSV);
    for (int o = 0; o < NC; o++) {
        size_t idx = (((size_t)b * NC + o) * NT + t) * NF + f;
        out[idx] = (yv[o] - mu) * r * gp[o] + betap[o] + x[idx];
    }
}

// ---------------- launch ----------------------------------------------------
extern "C" void kernel_launch(void* const* d_in, const int* in_sizes, int n_in,
                              void* d_out, int out_size)
{
    const float* x     = (const float*)d_in[0];
    const float* Wq    = (const float*)d_in[1];
    const float* bq    = (const float*)d_in[2];
    const float* aq    = (const float*)d_in[3];
    const float* gq    = (const float*)d_in[4];
    const float* betaq = (const float*)d_in[5];
    const float* Wk    = (const float*)d_in[6];
    const float* bk    = (const float*)d_in[7];
    const float* ak    = (const float*)d_in[8];
    const float* gk    = (const float*)d_in[9];
    const float* betak = (const float*)d_in[10];
    const float* Wv    = (const float*)d_in[11];
    const float* bv    = (const float*)d_in[12];
    const float* av    = (const float*)d_in[13];
    const float* gv    = (const float*)d_in[14];
    const float* betav = (const float*)d_in[15];
    const float* Wp    = (const float*)d_in[16];
    const float* bp    = (const float*)d_in[17];
    const float* ap    = (const float*)d_in[18];
    const float* gp    = (const float*)d_in[19];
    const float* betap = (const float*)d_in[20];
    float* out = (float*)d_out;

    float *pQ, *pK, *pV, *pS, *pO;
    cudaGetSymbolAddress((void**)&pQ, g_Q);
    cudaGetSymbolAddress((void**)&pK, g_K);
    cudaGetSymbolAddress((void**)&pV, g_V);
    cudaGetSymbolAddress((void**)&pS, g_S);
    cudaGetSymbolAddress((void**)&pO, g_O);

    // 1) QKV projections
    qkv_kernel<<<dim3(NT / 4, NB), dim3(64, 4)>>>(
        x, Wq, bq, aq, gq, betaq, Wk, bk, ak, gk, betak, Wv, bv, av, gv, betav);

    // 2) S = (1/16) * Q K^T   per (h,b)
    sgemm_nt<<<dim3(NT / 128, NT / 128, NHB), 256>>>(
        pQ, pK, pS, NT, NT, DQK, 0.0625f,
        (size_t)NT * DQK, (size_t)NT * DQK, (size_t)NT * NT);

    // 3) softmax rows
    softmax_kernel<<<NHB * NT, 256>>>(pS);

    // 4) O = P V
    sgemm_nn<<<dim3(DV / 128, NT / 128, NHB), 256>>>(
        pS, pV, pO, NT, DV, NT,
        (size_t)NT * NT, (size_t)NT * DV, (size_t)NT * DV);

    // 5) output projection + LN + residual
    out_kernel<<<dim3(NT / 4, NB), dim3(64, 4)>>>(
        x, Wp, bp, ap, gp, betap, out);
}

// round 3
// speedup vs baseline: 2.3237x; 2.3237x over previous
#include <cuda_runtime.h>
#include <cstdint>
#include <cstddef>

#define EPSV 1e-5f

// problem dims (fixed)
#define NB 2
#define NC 64
#define NT 2048
#define NF 64
#define NH 4
#define NHC 4
#define NVC 16
#define DQK 256   // NHC*NF
#define DV  1024  // NVC*NF
#define NHB 8     // NH*NB

// ---------------- scratch (device globals; no allocations allowed) ----------
__device__ float g_Q[(size_t)NHB * NT * DQK];   // 16 MB
__device__ float g_K[(size_t)NHB * NT * DQK];   // 16 MB
__device__ float g_V[(size_t)NHB * NT * DV];    // 64 MB
__device__ float g_Vt[(size_t)NHB * DV * NT];   // 64 MB (V transposed: [dv][t])
__device__ float g_S[(size_t)NHB * NT * NT];    // 128 MB
__device__ float g_O[(size_t)NHB * NT * DV];    // 64 MB

// ---------------- helpers ----------------------------------------------------
__device__ __forceinline__ uint32_t smem_u32(const void* p) {
    uint32_t a;
    asm("{ .reg .u64 t; cvta.to.shared.u64 t, %1; cvt.u32.u64 %0, t; }" : "=r"(a) : "l"(p));
    return a;
}
__device__ __forceinline__ float to_tf32(float x) {
    asm("cvt.rna.tf32.f32 %0, %1;" : "=f"(x) : "f"(x));
    return x;
}
__device__ __forceinline__ void cp_async16(uint32_t dst, const void* src) {
    asm volatile("cp.async.cg.shared.global [%0], [%1], 16;" :: "r"(dst), "l"(src) : "memory");
}
__device__ __forceinline__ void cp_commit() { asm volatile("cp.async.commit_group;" ::: "memory"); }
template <int N> __device__ __forceinline__ void cp_wait() {
    asm volatile("cp.async.wait_group %0;" :: "n"(N) : "memory");
}
__device__ __forceinline__ void mma_tf32(float* c, const uint32_t* a, const uint32_t* b) {
    asm volatile(
        "mma.sync.aligned.m16n8k8.row.col.f32.tf32.tf32.f32 "
        "{%0,%1,%2,%3}, {%4,%5,%6,%7}, {%8,%9}, {%0,%1,%2,%3};"
        : "+f"(c[0]), "+f"(c[1]), "+f"(c[2]), "+f"(c[3])
        : "r"(a[0]), "r"(a[1]), "r"(a[2]), "r"(a[3]), "r"(b[0]), "r"(b[1]));
}

// ---------------- tensor-core (mma.sync tf32) GEMM ---------------------------
// C[M,N] = alpha * A[M,K] * B[N,K]^T.  A,B row-major.  Tile 128x128, BK=32.
// 8 warps, warp tile 64(M) x 32(N). Smem row stride 36 floats (conflict-free frags).
#define BM 128
#define BN 128
#define BK 32
#define LDS_STRIDE 36                      // floats; bank(m)=(4m+k)%32 distinct
#define TILE_FLOATS (BM * LDS_STRIDE)      // 4608 floats = 18432 B (A or B tile)
#define STAGE_BYTES (2 * TILE_FLOATS * 4)  // 36864
#define NSTG 3
#define SMEM_GEMM (NSTG * STAGE_BYTES)     // 110592

__global__ __launch_bounds__(256) void gemm_mma(
    const float* __restrict__ A, const float* __restrict__ B, float* __restrict__ C,
    int K, int Nld, float alpha, size_t sA, size_t sB, size_t sC)
{
    extern __shared__ char smem[];
    const int tid = threadIdx.x;
    const int wid = tid >> 5;
    const int lane = tid & 31;
    const int g = lane >> 2;       // group id 0..7
    const int tc = lane & 3;       // thread-in-group 0..3

    A += (size_t)blockIdx.z * sA;
    B += (size_t)blockIdx.z * sB;
    C += (size_t)blockIdx.z * sC;
    const int bm = blockIdx.y * BM;
    const int bn = blockIdx.x * BN;

    const int wm = (wid & 1) * 64;   // warp M offset
    const int wn = (wid >> 1) * 32;  // warp N offset

    float acc[4][4][4];
#pragma unroll
    for (int mt = 0; mt < 4; mt++)
#pragma unroll
        for (int nt = 0; nt < 4; nt++)
#pragma unroll
            for (int i = 0; i < 4; i++) acc[mt][nt][i] = 0.f;

    const int nk = K / BK;

#define ISSUE(it) do {                                                         \
        int _st = (it) % NSTG;                                                 \
        uint32_t _as = smem_u32(smem) + _st * STAGE_BYTES;                     \
        uint32_t _bs = _as + TILE_FLOATS * 4;                                  \
        const float* _ga = A + (size_t)bm * K + (size_t)(it) * BK;             \
        const float* _gb = B + (size_t)bn * K + (size_t)(it) * BK;             \
        _Pragma("unroll")                                                      \
        for (int j = 0; j < 4; j++) {                                          \
            int idx = tid + j * 256;                                           \
            int row = idx >> 3, c = (idx & 7) * 4;                             \
            cp_async16(_as + (uint32_t)(row * LDS_STRIDE + c) * 4,             \
                       _ga + (size_t)row * K + c);                             \
        }                                                                      \
        _Pragma("unroll")                                                      \
        for (int j = 0; j < 4; j++) {                                          \
            int idx = tid + j * 256;                                           \
            int row = idx >> 3, c = (idx & 7) * 4;                             \
            cp_async16(_bs + (uint32_t)(row * LDS_STRIDE + c) * 4,             \
                       _gb + (size_t)row * K + c);                             \
        }                                                                      \
        cp_commit();                                                           \
    } while (0)

    ISSUE(0);
    ISSUE(1);

    for (int it = 0; it < nk; it++) {
        if (it < nk - 1) cp_wait<1>(); else cp_wait<0>();
        __syncthreads();
        if (it + 2 < nk) ISSUE(it + 2);

        const float* As = (const float*)(smem + (it % NSTG) * STAGE_BYTES);
        const float* Bs = As + TILE_FLOATS;

#pragma unroll
        for (int ks = 0; ks < 4; ks++) {
            const int k0 = ks * 8;
            uint32_t a[4][4], b[4][2];
#pragma unroll
            for (int mt = 0; mt < 4; mt++) {
                int m0 = wm + mt * 16 + g;
                a[mt][0] = __float_as_uint(As[m0 * LDS_STRIDE + k0 + tc]);
                a[mt][1] = __float_as_uint(As[(m0 + 8) * LDS_STRIDE + k0 + tc]);
                a[mt][2] = __float_as_uint(As[m0 * LDS_STRIDE + k0 + tc + 4]);
                a[mt][3] = __float_as_uint(As[(m0 + 8) * LDS_STRIDE + k0 + tc + 4]);
            }
#pragma unroll
            for (int nt = 0; nt < 4; nt++) {
                int n0 = wn + nt * 8 + g;
                b[nt][0] = __float_as_uint(Bs[n0 * LDS_STRIDE + k0 + tc]);
                b[nt][1] = __float_as_uint(Bs[n0 * LDS_STRIDE + k0 + tc + 4]);
            }
#pragma unroll
            for (int mt = 0; mt < 4; mt++)
#pragma unroll
                for (int nt = 0; nt < 4; nt++)
                    mma_tf32(acc[mt][nt], a[mt], b[nt]);
        }
    }
#undef ISSUE

    // epilogue: direct vectorized stores
#pragma unroll
    for (int mt = 0; mt < 4; mt++) {
#pragma unroll
        for (int nt = 0; nt < 4; nt++) {
            int row = bm + wm + mt * 16 + g;
            int col = bn + wn + nt * 8 + 2 * tc;
            float2 v0 = make_float2(acc[mt][nt][0] * alpha, acc[mt][nt][1] * alpha);
            float2 v1 = make_float2(acc[mt][nt][2] * alpha, acc[mt][nt][3] * alpha);
            *(float2*)&C[(size_t)row * Nld + col] = v0;
            *(float2*)&C[(size_t)(row + 8) * Nld + col] = v1;
        }
    }
}

// ---------------- kernel 1: QKV projection + PReLU + per-head LN ------------
__global__ __launch_bounds__(256) void qkv_kernel(
    const float* __restrict__ x,
    const float* __restrict__ Wq, const float* __restrict__ bq, const float* __restrict__ aq,
    const float* __restrict__ gq, const float* __restrict__ betaq,
    const float* __restrict__ Wk, const float* __restrict__ bk, const float* __restrict__ ak,
    const float* __restrict__ gk, const float* __restrict__ betak,
    const float* __restrict__ Wv, const float* __restrict__ bv, const float* __restrict__ av,
    const float* __restrict__ gv, const float* __restrict__ betav)
{
    __shared__ float sWq[NH * NHC * NC];
    __shared__ float sWk[NH * NHC * NC];
    __shared__ float sWv[NH * NVC * NC];

    int tid = threadIdx.y * 64 + threadIdx.x;
    for (int i = tid; i < NH * NHC * NC; i += 256) { sWq[i] = Wq[i]; sWk[i] = Wk[i]; }
    for (int i = tid; i < NH * NVC * NC; i += 256) { sWv[i] = Wv[i]; }
    __syncthreads();

    int f = threadIdx.x;
    int t = blockIdx.x * 4 + threadIdx.y;
    int b = blockIdx.y;

    const float* xp = x + ((size_t)b * NC * NT + t) * NF + f;

    for (int h = 0; h < NH; h++) {
        float q[NHC], k[NHC], v[NVC];
#pragma unroll
        for (int j = 0; j < NHC; j++) { q[j] = 0.f; k[j] = 0.f; }
#pragma unroll
        for (int j = 0; j < NVC; j++) v[j] = 0.f;

        for (int c0 = 0; c0 < NC; c0 += 4) {
            float xc0 = xp[(size_t)(c0 + 0) * NT * NF];
            float xc1 = xp[(size_t)(c0 + 1) * NT * NF];
            float xc2 = xp[(size_t)(c0 + 2) * NT * NF];
            float xc3 = xp[(size_t)(c0 + 3) * NT * NF];
#pragma unroll
            for (int j = 0; j < NHC; j++) {
                float4 w = *(const float4*)&sWq[(h * NHC + j) * NC + c0];
                q[j] += w.x * xc0 + w.y * xc1 + w.z * xc2 + w.w * xc3;
            }
#pragma unroll
            for (int j = 0; j < NHC; j++) {
                float4 w = *(const float4*)&sWk[(h * NHC + j) * NC + c0];
                k[j] += w.x * xc0 + w.y * xc1 + w.z * xc2 + w.w * xc3;
            }
#pragma unroll
            for (int j = 0; j < NVC; j++) {
                float4 w = *(const float4*)&sWv[(h * NVC + j) * NC + c0];
                v[j] += w.x * xc0 + w.y * xc1 + w.z * xc2 + w.w * xc3;
            }
        }
        {
            float a = aq[h], mu = 0.f;
#pragma unroll
            for (int j = 0; j < NHC; j++) {
                float y = q[j] + bq[h * NHC + j];
                y = (y >= 0.f) ? y : a * y; q[j] = y; mu += y;
            }
            mu *= (1.f / NHC);
            float var = 0.f;
#pragma unroll
            for (int j = 0; j < NHC; j++) { float d = q[j] - mu; var += d * d; }
            float r = rsqrtf(var * (1.f / NHC) + EPSV);
#pragma unroll
            for (int j = 0; j < NHC; j++) {
                float o = (q[j] - mu) * r * gq[h * NHC + j] + betaq[h * NHC + j];
                g_Q[((size_t)(h * NB + b) * NT + t) * DQK + j * NF + f] = to_tf32(o);
            }
        }
        {
            float a = ak[h], mu = 0.f;
#pragma unroll
            for (int j = 0; j < NHC; j++) {
                float y = k[j] + bk[h * NHC + j];
                y = (y >= 0.f) ? y : a * y; k[j] = y; mu += y;
            }
            mu *= (1.f / NHC);
            float var = 0.f;
#pragma unroll
            for (int j = 0; j < NHC; j++) { float d = k[j] - mu; var += d * d; }
            float r = rsqrtf(var * (1.f / NHC) + EPSV);
#pragma unroll
            for (int j = 0; j < NHC; j++) {
                float o = (k[j] - mu) * r * gk[h * NHC + j] + betak[h * NHC + j];
                g_K[((size_t)(h * NB + b) * NT + t) * DQK + j * NF + f] = to_tf32(o);
            }
        }
        {
            float a = av[h], mu = 0.f;
#pragma unroll
            for (int j = 0; j < NVC; j++) {
                float y = v[j] + bv[h * NVC + j];
                y = (y >= 0.f) ? y : a * y; v[j] = y; mu += y;
            }
            mu *= (1.f / NVC);
            float var = 0.f;
#pragma unroll
            for (int j = 0; j < NVC; j++) { float d = v[j] - mu; var += d * d; }
            float r = rsqrtf(var * (1.f / NVC) + EPSV);
#pragma unroll
            for (int j = 0; j < NVC; j++) {
                float o = (v[j] - mu) * r * gv[h * NVC + j] + betav[h * NVC + j];
                g_V[((size_t)(h * NB + b) * NT + t) * DV + j * NF + f] = to_tf32(o);
            }
        }
    }
}

// ---------------- transpose V: [t][dv] -> [dv][t] per batch ------------------
__global__ __launch_bounds__(256) void transpose_v()
{
    __shared__ float tile[32][33];
    int bt = blockIdx.x * 32, bd = blockIdx.y * 32;
    size_t base = (size_t)blockIdx.z * NT * DV;
    int tx = threadIdx.x, ty = threadIdx.y;
#pragma unroll
    for (int j = 0; j < 4; j++)
        tile[ty + j * 8][tx] = g_V[base + (size_t)(bt + ty + j * 8) * DV + bd + tx];
    __syncthreads();
#pragma unroll
    for (int j = 0; j < 4; j++)
        g_Vt[base + (size_t)(bd + ty + j * 8) * NT + bt + tx] = tile[tx][ty + j * 8];
}

// ---------------- softmax rows (writes tf32-rounded P) -----------------------
__global__ __launch_bounds__(256) void softmax_kernel(float* __restrict__ S)
{
    __shared__ float red[256];
    float* p = S + (size_t)blockIdx.x * NT;
    int tid = threadIdx.x;

    float v[8];
    float m = -1e30f;
#pragma unroll
    for (int i = 0; i < 8; i++) { v[i] = p[tid + i * 256]; m = fmaxf(m, v[i]); }
    red[tid] = m; __syncthreads();
#pragma unroll
    for (int s = 128; s > 0; s >>= 1) {
        if (tid < s) red[tid] = fmaxf(red[tid], red[tid + s]);
        __syncthreads();
    }
    m = red[0];
    __syncthreads();

    float sum = 0.f;
#pragma unroll
    for (int i = 0; i < 8; i++) { v[i] = __expf(v[i] - m); sum += v[i]; }
    red[tid] = sum; __syncthreads();
#pragma unroll
    for (int s = 128; s > 0; s >>= 1) {
        if (tid < s) red[tid] += red[tid + s];
        __syncthreads();
    }
    float inv = 1.f / red[0];
#pragma unroll
    for (int i = 0; i < 8; i++) p[tid + i * 256] = to_tf32(v[i] * inv);
}

// ---------------- output projection + PReLU + LN + residual ------------------
__global__ __launch_bounds__(256) void out_kernel(
    const float* __restrict__ x,
    const float* __restrict__ Wp, const float* __restrict__ bp, const float* __restrict__ ap,
    const float* __restrict__ gp, const float* __restrict__ betap,
    float* __restrict__ out)
{
    __shared__ float sW[NC * NC];
    int tid = threadIdx.y * 64 + threadIdx.x;
    for (int i = tid; i < NC * NC; i += 256) sW[i] = Wp[i];
    __syncthreads();

    int f = threadIdx.x;
    int t = blockIdx.x * 4 + threadIdx.y;
    int b = blockIdx.y;

    float Og[NC];
#pragma unroll
    for (int c = 0; c < NC; c++) {
        int h = c >> 4, vc = c & 15;
        Og[c] = g_O[((size_t)(h * NB + b) * NT + t) * DV + vc * NF + f];
    }

    float a = ap[0];
    float yv[NC];
    float s1 = 0.f, s2 = 0.f;
    for (int o = 0; o < NC; o++) {
        float acc = bp[o];
#pragma unroll
        for (int c0 = 0; c0 < NC; c0 += 4) {
            float4 w = *(const float4*)&sW[o * NC + c0];
            acc += w.x * Og[c0] + w.y * Og[c0 + 1] + w.z * Og[c0 + 2] + w.w * Og[c0 + 3];
        }
        acc = (acc >= 0.f) ? acc : a * acc;
        yv[o] = acc;
        s1 += acc; s2 += acc * acc;
    }
    float mu = s1 * (1.f / NC);
    float var = s2 * (1.f / NC) - mu * mu;
    float r = rsqrtf(var + EPSV);
    for (int o = 0; o < NC; o++) {
        size_t idx = (((size_t)b * NC + o) * NT + t) * NF + f;
        out[idx] = (yv[o] - mu) * r * gp[o] + betap[o] + x[idx];
    }
}

// ---------------- launch ------------------------------------------------------
extern "C" void kernel_launch(void* const* d_in, const int* in_sizes, int n_in,
                              void* d_out, int out_size)
{
    const float* x     = (const float*)d_in[0];
    const float* Wq    = (const float*)d_in[1];
    const float* bq    = (const float*)d_in[2];
    const float* aq    = (const float*)d_in[3];
    const float* gq    = (const float*)d_in[4];
    const float* betaq = (const float*)d_in[5];
    const float* Wk    = (const float*)d_in[6];
    const float* bk    = (const float*)d_in[7];
    const float* ak    = (const float*)d_in[8];
    const float* gk    = (const float*)d_in[9];
    const float* betak = (const float*)d_in[10];
    const float* Wv    = (const float*)d_in[11];
    const float* bv    = (const float*)d_in[12];
    const float* av    = (const float*)d_in[13];
    const float* gv    = (const float*)d_in[14];
    const float* betav = (const float*)d_in[15];
    const float* Wp    = (const float*)d_in[16];
    const float* bp    = (const float*)d_in[17];
    const float* ap    = (const float*)d_in[18];
    const float* gp    = (const float*)d_in[19];
    const float* betap = (const float*)d_in[20];
    float* out = (float*)d_out;

    float *pQ, *pK, *pVt, *pS, *pO;
    cudaGetSymbolAddress((void**)&pQ, g_Q);
    cudaGetSymbolAddress((void**)&pK, g_K);
    cudaGetSymbolAddress((void**)&pVt, g_Vt);
    cudaGetSymbolAddress((void**)&pS, g_S);
    cudaGetSymbolAddress((void**)&pO, g_O);

    cudaFuncSetAttribute(gemm_mma, cudaFuncAttributeMaxDynamicSharedMemorySize, SMEM_GEMM);

    // 1) QKV projections (+tf32 rounding)
    qkv_kernel<<<dim3(NT / 4, NB), dim3(64, 4)>>>(
        x, Wq, bq, aq, gq, betaq, Wk, bk, ak, gk, betak, Wv, bv, av, gv, betav);

    // 2) V transpose
    transpose_v<<<dim3(NT / 32, DV / 32, NHB), dim3(32, 8)>>>();

    // 3) S = (1/16) Q K^T  (tf32 mma.sync)
    gemm_mma<<<dim3(NT / BN, NT / BM, NHB), 256, SMEM_GEMM>>>(
        pQ, pK, pS, DQK, NT, 0.0625f,
        (size_t)NT * DQK, (size_t)NT * DQK, (size_t)NT * NT);

    // 4) softmax rows (+tf32 rounding)
    softmax_kernel<<<NHB * NT, 256>>>(pS);

    // 5) O = P V  (tf32 mma.sync; B = V^T K-major)
    gemm_mma<<<dim3(DV / BN, NT / BM, NHB), 256, SMEM_GEMM>>>(
        pS, pVt, pO, NT, DV, 1.0f,
        (size_t)NT * NT, (size_t)DV * NT, (size_t)NT * DV);

    // 6) output projection + LN + residual
    out_kernel<<<dim3(NT / 4, NB), dim3(64, 4)>>>(
        x, Wp, bp, ap, gp, betap, out);
}

// round 4
// speedup vs baseline: 2.4695x; 1.0627x over previous
#include <cuda_runtime.h>
#include <cstdint>
#include <cstddef>

#define EPSV 1e-5f

// problem dims (fixed)
#define NB 2
#define NC 64
#define NT 2048
#define NF 64
#define NH 4
#define NHC 4
#define NVC 16
#define DQK 256   // NHC*NF
#define DV  1024  // NVC*NF
#define NHB 8     // NH*NB

// ---------------- scratch (device globals; no allocations allowed) ----------
__device__ float g_Q[(size_t)NHB * NT * DQK];   // 16 MB
__device__ float g_K[(size_t)NHB * NT * DQK];   // 16 MB
__device__ float g_V[(size_t)NHB * NT * DV];    // 64 MB
__device__ float g_Vt[(size_t)NHB * DV * NT];   // 64 MB (V transposed: [dv][t])
__device__ float g_S[(size_t)NHB * NT * NT];    // 128 MB
__device__ float g_O[(size_t)NHB * NT * DV];    // 64 MB

// ---------------- helpers ----------------------------------------------------
__device__ __forceinline__ uint32_t smem_u32(const void* p) {
    uint32_t a;
    asm("{ .reg .u64 t; cvta.to.shared.u64 t, %1; cvt.u32.u64 %0, t; }" : "=r"(a) : "l"(p));
    return a;
}
__device__ __forceinline__ float to_tf32(float x) {
    asm("cvt.rna.tf32.f32 %0, %1;" : "=f"(x) : "f"(x));
    return x;
}
__device__ __forceinline__ void cp_async16(uint32_t dst, const void* src) {
    asm volatile("cp.async.cg.shared.global [%0], [%1], 16;" :: "r"(dst), "l"(src) : "memory");
}
__device__ __forceinline__ void cp_commit() { asm volatile("cp.async.commit_group;" ::: "memory"); }
template <int N> __device__ __forceinline__ void cp_wait() {
    asm volatile("cp.async.wait_group %0;" :: "n"(N) : "memory");
}
__device__ __forceinline__ void mma_tf32(float* c, const uint32_t* a, const uint32_t* b) {
    asm volatile(
        "mma.sync.aligned.m16n8k8.row.col.f32.tf32.tf32.f32 "
        "{%0,%1,%2,%3}, {%4,%5,%6,%7}, {%8,%9}, {%0,%1,%2,%3};"
        : "+f"(c[0]), "+f"(c[1]), "+f"(c[2]), "+f"(c[3])
        : "r"(a[0]), "r"(a[1]), "r"(a[2]), "r"(a[3]), "r"(b[0]), "r"(b[1]));
}

// ---------------- tensor-core (mma.sync tf32) GEMM ---------------------------
// C[M,N] = alpha * A[M,K] * B[N,K]^T.  A,B row-major.  Tile 128x256, BK=32.
// 8 warps as 2(M) x 4(N); warp tile 64(M) x 64(N).
// Smem row stride 36 floats => fragment banks (4g+tc)%32 all distinct.
#define BM 128
#define BN 256
#define BK 32
#define LDS_STRIDE 36
#define A_TILE_FLOATS (BM * LDS_STRIDE)            // 4608
#define B_TILE_FLOATS (BN * LDS_STRIDE)            // 9216
#define STAGE_BYTES ((A_TILE_FLOATS + B_TILE_FLOATS) * 4)   // 55296
#define NSTG 3
#define SMEM_GEMM (NSTG * STAGE_BYTES)             // 165888

__global__ __launch_bounds__(256, 1) void gemm_mma(
    const float* __restrict__ A, const float* __restrict__ B, float* __restrict__ C,
    int K, int Nld, float alpha, size_t sA, size_t sB, size_t sC)
{
    extern __shared__ char smem[];
    const int tid = threadIdx.x;
    const int wid = tid >> 5;
    const int lane = tid & 31;
    const int g = lane >> 2;       // 0..7
    const int tc = lane & 3;       // 0..3

    A += (size_t)blockIdx.z * sA;
    B += (size_t)blockIdx.z * sB;
    C += (size_t)blockIdx.z * sC;
    const int bm = blockIdx.y * BM;
    const int bn = blockIdx.x * BN;

    const int wm = (wid & 1) * 64;   // warp M offset (0/64)
    const int wn = (wid >> 1) * 64;  // warp N offset (0/64/128/192)

    float acc[4][8][4];
#pragma unroll
    for (int mt = 0; mt < 4; mt++)
#pragma unroll
        for (int nt = 0; nt < 8; nt++)
#pragma unroll
            for (int i = 0; i < 4; i++) acc[mt][nt][i] = 0.f;

    const int nk = K / BK;

#define ISSUE(it) do {                                                         \
        int _st = (it) % NSTG;                                                 \
        uint32_t _as = smem_u32(smem) + _st * STAGE_BYTES;                     \
        uint32_t _bs = _as + A_TILE_FLOATS * 4;                                \
        const float* _ga = A + (size_t)bm * K + (size_t)(it) * BK;             \
        const float* _gb = B + (size_t)bn * K + (size_t)(it) * BK;             \
        _Pragma("unroll")                                                      \
        for (int j = 0; j < 4; j++) {                                          \
            int idx = tid + j * 256;                                           \
            int row = idx >> 3, c = (idx & 7) * 4;                             \
            cp_async16(_as + (uint32_t)(row * LDS_STRIDE + c) * 4,             \
                       _ga + (size_t)row * K + c);                             \
        }                                                                      \
        _Pragma("unroll")                                                      \
        for (int j = 0; j < 8; j++) {                                          \
            int idx = tid + j * 256;                                           \
            int row = idx >> 3, c = (idx & 7) * 4;                             \
            cp_async16(_bs + (uint32_t)(row * LDS_STRIDE + c) * 4,             \
                       _gb + (size_t)row * K + c);                             \
        }                                                                      \
        cp_commit();                                                           \
    } while (0)

    ISSUE(0);
    ISSUE(1);

    for (int it = 0; it < nk; it++) {
        if (it < nk - 1) cp_wait<1>(); else cp_wait<0>();
        __syncthreads();
        if (it + 2 < nk) ISSUE(it + 2);

        const float* As = (const float*)(smem + (it % NSTG) * STAGE_BYTES);
        const float* Bs = As + A_TILE_FLOATS;

#pragma unroll
        for (int ks = 0; ks < 4; ks++) {
            const int k0 = ks * 8;
            uint32_t a[4][4], b[8][2];
#pragma unroll
            for (int mt = 0; mt < 4; mt++) {
                int m0 = wm + mt * 16 + g;
                a[mt][0] = __float_as_uint(As[m0 * LDS_STRIDE + k0 + tc]);
                a[mt][1] = __float_as_uint(As[(m0 + 8) * LDS_STRIDE + k0 + tc]);
                a[mt][2] = __float_as_uint(As[m0 * LDS_STRIDE + k0 + tc + 4]);
                a[mt][3] = __float_as_uint(As[(m0 + 8) * LDS_STRIDE + k0 + tc + 4]);
            }
#pragma unroll
            for (int nt = 0; nt < 8; nt++) {
                int n0 = wn + nt * 8 + g;
                b[nt][0] = __float_as_uint(Bs[n0 * LDS_STRIDE + k0 + tc]);
                b[nt][1] = __float_as_uint(Bs[n0 * LDS_STRIDE + k0 + tc + 4]);
            }
#pragma unroll
            for (int mt = 0; mt < 4; mt++)
#pragma unroll
                for (int nt = 0; nt < 8; nt++)
                    mma_tf32(acc[mt][nt], a[mt], b[nt]);
        }
    }
#undef ISSUE

    // epilogue: direct vectorized stores
#pragma unroll
    for (int mt = 0; mt < 4; mt++) {
#pragma unroll
        for (int nt = 0; nt < 8; nt++) {
            int row = bm + wm + mt * 16 + g;
            int col = bn + wn + nt * 8 + 2 * tc;
            float2 v0 = make_float2(acc[mt][nt][0] * alpha, acc[mt][nt][1] * alpha);
            float2 v1 = make_float2(acc[mt][nt][2] * alpha, acc[mt][nt][3] * alpha);
            *(float2*)&C[(size_t)row * Nld + col] = v0;
            *(float2*)&C[(size_t)(row + 8) * Nld + col] = v1;
        }
    }
}

// ---------------- kernel 1: QKV projection + PReLU + per-head LN ------------
__global__ __launch_bounds__(256) void qkv_kernel(
    const float* __restrict__ x,
    const float* __restrict__ Wq, const float* __restrict__ bq, const float* __restrict__ aq,
    const float* __restrict__ gq, const float* __restrict__ betaq,
    const float* __restrict__ Wk, const float* __restrict__ bk, const float* __restrict__ ak,
    const float* __restrict__ gk, const float* __restrict__ betak,
    const float* __restrict__ Wv, const float* __restrict__ bv, const float* __restrict__ av,
    const float* __restrict__ gv, const float* __restrict__ betav)
{
    __shared__ float sWq[NH * NHC * NC];
    __shared__ float sWk[NH * NHC * NC];
    __shared__ float sWv[NH * NVC * NC];

    int tid = threadIdx.y * 64 + threadIdx.x;
    for (int i = tid; i < NH * NHC * NC; i += 256) { sWq[i] = Wq[i]; sWk[i] = Wk[i]; }
    for (int i = tid; i < NH * NVC * NC; i += 256) { sWv[i] = Wv[i]; }
    __syncthreads();

    int f = threadIdx.x;
    int t = blockIdx.x * 4 + threadIdx.y;
    int b = blockIdx.y;

    const float* xp = x + ((size_t)b * NC * NT + t) * NF + f;

    for (int h = 0; h < NH; h++) {
        float q[NHC], k[NHC], v[NVC];
#pragma unroll
        for (int j = 0; j < NHC; j++) { q[j] = 0.f; k[j] = 0.f; }
#pragma unroll
        for (int j = 0; j < NVC; j++) v[j] = 0.f;

        for (int c0 = 0; c0 < NC; c0 += 4) {
            float xc0 = xp[(size_t)(c0 + 0) * NT * NF];
            float xc1 = xp[(size_t)(c0 + 1) * NT * NF];
            float xc2 = xp[(size_t)(c0 + 2) * NT * NF];
            float xc3 = xp[(size_t)(c0 + 3) * NT * NF];
#pragma unroll
            for (int j = 0; j < NHC; j++) {
                float4 w = *(const float4*)&sWq[(h * NHC + j) * NC + c0];
                q[j] += w.x * xc0 + w.y * xc1 + w.z * xc2 + w.w * xc3;
            }
#pragma unroll
            for (int j = 0; j < NHC; j++) {
                float4 w = *(const float4*)&sWk[(h * NHC + j) * NC + c0];
                k[j] += w.x * xc0 + w.y * xc1 + w.z * xc2 + w.w * xc3;
            }
#pragma unroll
            for (int j = 0; j < NVC; j++) {
                float4 w = *(const float4*)&sWv[(h * NVC + j) * NC + c0];
                v[j] += w.x * xc0 + w.y * xc1 + w.z * xc2 + w.w * xc3;
            }
        }
        {
            float a = aq[h], mu = 0.f;
#pragma unroll
            for (int j = 0; j < NHC; j++) {
                float y = q[j] + bq[h * NHC + j];
                y = (y >= 0.f) ? y : a * y; q[j] = y; mu += y;
            }
            mu *= (1.f / NHC);
            float var = 0.f;
#pragma unroll
            for (int j = 0; j < NHC; j++) { float d = q[j] - mu; var += d * d; }
            float r = rsqrtf(var * (1.f / NHC) + EPSV);
#pragma unroll
            for (int j = 0; j < NHC; j++) {
                float o = (q[j] - mu) * r * gq[h * NHC + j] + betaq[h * NHC + j];
                g_Q[((size_t)(h * NB + b) * NT + t) * DQK + j * NF + f] = to_tf32(o);
            }
        }
        {
            float a = ak[h], mu = 0.f;
#pragma unroll
            for (int j = 0; j < NHC; j++) {
                float y = k[j] + bk[h * NHC + j];
                y = (y >= 0.f) ? y : a * y; k[j] = y; mu += y;
            }
            mu *= (1.f / NHC);
            float var = 0.f;
#pragma unroll
            for (int j = 0; j < NHC; j++) { float d = k[j] - mu; var += d * d; }
            float r = rsqrtf(var * (1.f / NHC) + EPSV);
#pragma unroll
            for (int j = 0; j < NHC; j++) {
                float o = (k[j] - mu) * r * gk[h * NHC + j] + betak[h * NHC + j];
                g_K[((size_t)(h * NB + b) * NT + t) * DQK + j * NF + f] = to_tf32(o);
            }
        }
        {
            float a = av[h], mu = 0.f;
#pragma unroll
            for (int j = 0; j < NVC; j++) {
                float y = v[j] + bv[h * NVC + j];
                y = (y >= 0.f) ? y : a * y; v[j] = y; mu += y;
            }
            mu *= (1.f / NVC);
            float var = 0.f;
#pragma unroll
            for (int j = 0; j < NVC; j++) { float d = v[j] - mu; var += d * d; }
            float r = rsqrtf(var * (1.f / NVC) + EPSV);
#pragma unroll
            for (int j = 0; j < NVC; j++) {
                float o = (v[j] - mu) * r * gv[h * NVC + j] + betav[h * NVC + j];
                g_V[((size_t)(h * NB + b) * NT + t) * DV + j * NF + f] = to_tf32(o);
            }
        }
    }
}

// ---------------- transpose V: [t][dv] -> [dv][t] per batch ------------------
__global__ __launch_bounds__(256) void transpose_v()
{
    __shared__ float tile[32][33];
    int bt = blockIdx.x * 32, bd = blockIdx.y * 32;
    size_t base = (size_t)blockIdx.z * NT * DV;
    int tx = threadIdx.x, ty = threadIdx.y;
#pragma unroll
    for (int j = 0; j < 4; j++)
        tile[ty + j * 8][tx] = g_V[base + (size_t)(bt + ty + j * 8) * DV + bd + tx];
    __syncthreads();
#pragma unroll
    for (int j = 0; j < 4; j++)
        g_Vt[base + (size_t)(bd + ty + j * 8) * NT + bt + tx] = tile[tx][ty + j * 8];
}

// ---------------- softmax rows (float4 + shuffle reductions) -----------------
__global__ __launch_bounds__(256) void softmax_kernel(float* __restrict__ S)
{
    __shared__ float red[8];
    float4* p = (float4*)(S + (size_t)blockIdx.x * NT);
    int tid = threadIdx.x;
    int lane = tid & 31, wid = tid >> 5;

    float4 v0 = p[tid];
    float4 v1 = p[tid + 256];
    float m = fmaxf(fmaxf(fmaxf(v0.x, v0.y), fmaxf(v0.z, v0.w)),
                    fmaxf(fmaxf(v1.x, v1.y), fmaxf(v1.z, v1.w)));
#pragma unroll
    for (int s = 16; s > 0; s >>= 1) m = fmaxf(m, __shfl_xor_sync(0xffffffffu, m, s));
    if (lane == 0) red[wid] = m;
    __syncthreads();
    m = red[lane & 7];
#pragma unroll
    for (int s = 4; s > 0; s >>= 1) m = fmaxf(m, __shfl_xor_sync(0xffffffffu, m, s));

    v0.x = __expf(v0.x - m); v0.y = __expf(v0.y - m);
    v0.z = __expf(v0.z - m); v0.w = __expf(v0.w - m);
    v1.x = __expf(v1.x - m); v1.y = __expf(v1.y - m);
    v1.z = __expf(v1.z - m); v1.w = __expf(v1.w - m);
    float sum = v0.x + v0.y + v0.z + v0.w + v1.x + v1.y + v1.z + v1.w;
#pragma unroll
    for (int s = 16; s > 0; s >>= 1) sum += __shfl_xor_sync(0xffffffffu, sum, s);
    __syncthreads();
    if (lane == 0) red[wid] = sum;
    __syncthreads();
    sum = red[lane & 7];
#pragma unroll
    for (int s = 4; s > 0; s >>= 1) sum += __shfl_xor_sync(0xffffffffu, sum, s);
    float inv = 1.f / sum;

    v0.x = to_tf32(v0.x * inv); v0.y = to_tf32(v0.y * inv);
    v0.z = to_tf32(v0.z * inv); v0.w = to_tf32(v0.w * inv);
    v1.x = to_tf32(v1.x * inv); v1.y = to_tf32(v1.y * inv);
    v1.z = to_tf32(v1.z * inv); v1.w = to_tf32(v1.w * inv);
    p[tid] = v0;
    p[tid + 256] = v1;
}

// ---------------- output projection + PReLU + LN + residual ------------------
__global__ __launch_bounds__(256) void out_kernel(
    const float* __restrict__ x,
    const float* __restrict__ Wp, const float* __restrict__ bp, const float* __restrict__ ap,
    const float* __restrict__ gp, const float* __restrict__ betap,
    float* __restrict__ out)
{
    __shared__ float sW[NC * NC];
    int tid = threadIdx.y * 64 + threadIdx.x;
    for (int i = tid; i < NC * NC; i += 256) sW[i] = Wp[i];
    __syncthreads();

    int f = threadIdx.x;
    int t = blockIdx.x * 4 + threadIdx.y;
    int b = blockIdx.y;

    float Og[NC];
#pragma unroll
    for (int c = 0; c < NC; c++) {
        int h = c >> 4, vc = c & 15;
        Og[c] = g_O[((size_t)(h * NB + b) * NT + t) * DV + vc * NF + f];
    }

    float a = ap[0];
    float yv[NC];
    float s1 = 0.f, s2 = 0.f;
    for (int o = 0; o < NC; o++) {
        float acc = bp[o];
#pragma unroll
        for (int c0 = 0; c0 < NC; c0 += 4) {
            float4 w = *(const float4*)&sW[o * NC + c0];
            acc += w.x * Og[c0] + w.y * Og[c0 + 1] + w.z * Og[c0 + 2] + w.w * Og[c0 + 3];
        }
        acc = (acc >= 0.f) ? acc : a * acc;
        yv[o] = acc;
        s1 += acc; s2 += acc * acc;
    }
    float mu = s1 * (1.f / NC);
    float var = s2 * (1.f / NC) - mu * mu;
    float r = rsqrtf(var + EPSV);
    for (int o = 0; o < NC; o++) {
        size_t idx = (((size_t)b * NC + o) * NT + t) * NF + f;
        out[idx] = (yv[o] - mu) * r * gp[o] + betap[o] + x[idx];
    }
}

// ---------------- launch ------------------------------------------------------
extern "C" void kernel_launch(void* const* d_in, const int* in_sizes, int n_in,
                              void* d_out, int out_size)
{
    const float* x     = (const float*)d_in[0];
    const float* Wq    = (const float*)d_in[1];
    const float* bq    = (const float*)d_in[2];
    const float* aq    = (const float*)d_in[3];
    const float* gq    = (const float*)d_in[4];
    const float* betaq = (const float*)d_in[5];
    const float* Wk    = (const float*)d_in[6];
    const float* bk    = (const float*)d_in[7];
    const float* ak    = (const float*)d_in[8];
    const float* gk    = (const float*)d_in[9];
    const float* betak = (const float*)d_in[10];
    const float* Wv    = (const float*)d_in[11];
    const float* bv    = (const float*)d_in[12];
    const float* av    = (const float*)d_in[13];
    const float* gv    = (const float*)d_in[14];
    const float* betav = (const float*)d_in[15];
    const float* Wp    = (const float*)d_in[16];
    const float* bp    = (const float*)d_in[17];
    const float* ap    = (const float*)d_in[18];
    const float* gp    = (const float*)d_in[19];
    const float* betap = (const float*)d_in[20];
    float* out = (float*)d_out;

    float *pQ, *pK, *pVt, *pS, *pO;
    cudaGetSymbolAddress((void**)&pQ, g_Q);
    cudaGetSymbolAddress((void**)&pK, g_K);
    cudaGetSymbolAddress((void**)&pVt, g_Vt);
    cudaGetSymbolAddress((void**)&pS, g_S);
    cudaGetSymbolAddress((void**)&pO, g_O);

    cudaFuncSetAttribute(gemm_mma, cudaFuncAttributeMaxDynamicSharedMemorySize, SMEM_GEMM);

    // 1) QKV projections (+tf32 rounding)
    qkv_kernel<<<dim3(NT / 4, NB), dim3(64, 4)>>>(
        x, Wq, bq, aq, gq, betaq, Wk, bk, ak, gk, betak, Wv, bv, av, gv, betav);

    // 2) V transpose
    transpose_v<<<dim3(NT / 32, DV / 32, NHB), dim3(32, 8)>>>();

    // 3) S = (1/16) Q K^T  (tf32 mma.sync)
    gemm_mma<<<dim3(NT / BN, NT / BM, NHB), 256, SMEM_GEMM>>>(
        pQ, pK, pS, DQK, NT, 0.0625f,
        (size_t)NT * DQK, (size_t)NT * DQK, (size_t)NT * NT);

    // 4) softmax rows (+tf32 rounding)
    softmax_kernel<<<NHB * NT, 256>>>(pS);

    // 5) O = P V  (tf32 mma.sync; B = V^T K-major)
    gemm_mma<<<dim3(DV / BN, NT / BM, NHB), 256, SMEM_GEMM>>>(
        pS, pVt, pO, NT, DV, 1.0f,
        (size_t)NT * NT, (size_t)DV * NT, (size_t)NT * DV);

    // 6) output projection + LN + residual
    out_kernel<<<dim3(NT / 4, NB), dim3(64, 4)>>>(
        x, Wp, bp, ap, gp, betap, out);
}

// round 5
// speedup vs baseline: 2.7142x; 1.0991x over previous
#include <cuda_runtime.h>
#include <cstdint>
#include <cstddef>

#define EPSV 1e-5f

// problem dims (fixed)
#define NB 2
#define NC 64
#define NT 2048
#define NF 64
#define NH 4
#define NHC 4
#define NVC 16
#define DQK 256   // NHC*NF
#define DV  1024  // NVC*NF
#define NHB 8     // NH*NB

// ---------------- scratch (device globals; no allocations allowed) ----------
__device__ float g_Q[(size_t)NHB * NT * DQK];   // 16 MB
__device__ float g_K[(size_t)NHB * NT * DQK];   // 16 MB
__device__ float g_V[(size_t)NHB * NT * DV];    // 64 MB
__device__ float g_E[(size_t)NHB * NT * NT];    // 128 MB  exp(alpha*S), unnormalized
__device__ float g_O[(size_t)NHB * NT * DV];    // 64 MB

// ---------------- helpers ----------------------------------------------------
__device__ __forceinline__ uint32_t smem_u32(const void* p) {
    uint32_t a;
    asm("{ .reg .u64 t; cvta.to.shared.u64 t, %1; cvt.u32.u64 %0, t; }" : "=r"(a) : "l"(p));
    return a;
}
__device__ __forceinline__ float to_tf32(float x) {
    asm("cvt.rna.tf32.f32 %0, %1;" : "=f"(x) : "f"(x));
    return x;
}
__device__ __forceinline__ void cp_async16(uint32_t dst, const void* src) {
    asm volatile("cp.async.cg.shared.global [%0], [%1], 16;" :: "r"(dst), "l"(src) : "memory");
}
__device__ __forceinline__ void cp_commit() { asm volatile("cp.async.commit_group;" ::: "memory"); }
template <int N> __device__ __forceinline__ void cp_wait() {
    asm volatile("cp.async.wait_group %0;" :: "n"(N) : "memory");
}
__device__ __forceinline__ void mma_tf32(float* c, const uint32_t* a, const uint32_t* b) {
    asm volatile(
        "mma.sync.aligned.m16n8k8.row.col.f32.tf32.tf32.f32 "
        "{%0,%1,%2,%3}, {%4,%5,%6,%7}, {%8,%9}, {%0,%1,%2,%3};"
        : "+f"(c[0]), "+f"(c[1]), "+f"(c[2]), "+f"(c[3])
        : "r"(a[0]), "r"(a[1]), "r"(a[2]), "r"(a[3]), "r"(b[0]), "r"(b[1]));
}

// ================= GEMM 1: E = tf32(exp(alpha * Q K^T)) ======================
// A,B row-major [*,K]. Tile 128x256, BK=32. 8 warps as 2(M)x4(N), warp 64x64.
#define BM 128
#define BN 256
#define BK 32
#define A_STRIDE 36
#define B_STRIDE 36
#define A_TILE_FLOATS (BM * A_STRIDE)                       // 4608
#define B1_TILE_FLOATS (BN * B_STRIDE)                      // 9216
#define STAGE1_BYTES ((A_TILE_FLOATS + B1_TILE_FLOATS) * 4) // 55296
#define NSTG 3
#define SMEM_G1 (NSTG * STAGE1_BYTES)                       // 165888

__global__ __launch_bounds__(256, 1) void gemm_qk_exp(
    const float* __restrict__ A, const float* __restrict__ B, float* __restrict__ C,
    float alpha, size_t sA, size_t sB, size_t sC)
{
    extern __shared__ char smem[];
    const int tid = threadIdx.x;
    const int wid = tid >> 5;
    const int lane = tid & 31;
    const int g = lane >> 2;
    const int tc = lane & 3;
    const int K = DQK;

    A += (size_t)blockIdx.z * sA;
    B += (size_t)blockIdx.z * sB;
    C += (size_t)blockIdx.z * sC;
    const int bm = blockIdx.y * BM;
    const int bn = blockIdx.x * BN;
    const int wm = (wid & 1) * 64;
    const int wn = (wid >> 1) * 64;

    float acc[4][8][4];
#pragma unroll
    for (int mt = 0; mt < 4; mt++)
#pragma unroll
        for (int nt = 0; nt < 8; nt++)
#pragma unroll
            for (int i = 0; i < 4; i++) acc[mt][nt][i] = 0.f;

    const int nk = K / BK;

#define ISSUE1(it) do {                                                        \
        int _st = (it) % NSTG;                                                 \
        uint32_t _as = smem_u32(smem) + _st * STAGE1_BYTES;                    \
        uint32_t _bs = _as + A_TILE_FLOATS * 4;                                \
        const float* _ga = A + (size_t)bm * K + (size_t)(it) * BK;             \
        const float* _gb = B + (size_t)bn * K + (size_t)(it) * BK;             \
        _Pragma("unroll")                                                      \
        for (int j = 0; j < 4; j++) {                                          \
            int idx = tid + j * 256;                                           \
            int row = idx >> 3, c = (idx & 7) * 4;                             \
            cp_async16(_as + (uint32_t)(row * A_STRIDE + c) * 4,               \
                       _ga + (size_t)row * K + c);                             \
        }                                                                      \
        _Pragma("unroll")                                                      \
        for (int j = 0; j < 8; j++) {                                          \
            int idx = tid + j * 256;                                           \
            int row = idx >> 3, c = (idx & 7) * 4;                             \
            cp_async16(_bs + (uint32_t)(row * B_STRIDE + c) * 4,               \
                       _gb + (size_t)row * K + c);                             \
        }                                                                      \
        cp_commit();                                                           \
    } while (0)

    ISSUE1(0);
    ISSUE1(1);

    for (int it = 0; it < nk; it++) {
        if (it < nk - 1) cp_wait<1>(); else cp_wait<0>();
        __syncthreads();
        if (it + 2 < nk) ISSUE1(it + 2);

        const float* As = (const float*)(smem + (it % NSTG) * STAGE1_BYTES);
        const float* Bs = As + A_TILE_FLOATS;

#pragma unroll
        for (int ks = 0; ks < 4; ks++) {
            const int k0 = ks * 8;
            uint32_t a[4][4], b[8][2];
#pragma unroll
            for (int mt = 0; mt < 4; mt++) {
                int m0 = wm + mt * 16 + g;
                a[mt][0] = __float_as_uint(As[m0 * A_STRIDE + k0 + tc]);
                a[mt][1] = __float_as_uint(As[(m0 + 8) * A_STRIDE + k0 + tc]);
                a[mt][2] = __float_as_uint(As[m0 * A_STRIDE + k0 + tc + 4]);
                a[mt][3] = __float_as_uint(As[(m0 + 8) * A_STRIDE + k0 + tc + 4]);
            }
#pragma unroll
            for (int nt = 0; nt < 8; nt++) {
                int n0 = wn + nt * 8 + g;
                b[nt][0] = __float_as_uint(Bs[n0 * B_STRIDE + k0 + tc]);
                b[nt][1] = __float_as_uint(Bs[n0 * B_STRIDE + k0 + tc + 4]);
            }
#pragma unroll
            for (int mt = 0; mt < 4; mt++)
#pragma unroll
                for (int nt = 0; nt < 8; nt++)
                    mma_tf32(acc[mt][nt], a[mt], b[nt]);
        }
    }
#undef ISSUE1

    // epilogue: E = tf32(exp(alpha * S))
#pragma unroll
    for (int mt = 0; mt < 4; mt++) {
#pragma unroll
        for (int nt = 0; nt < 8; nt++) {
            int row = bm + wm + mt * 16 + g;
            int col = bn + wn + nt * 8 + 2 * tc;
            float2 v0 = make_float2(to_tf32(__expf(acc[mt][nt][0] * alpha)),
                                    to_tf32(__expf(acc[mt][nt][1] * alpha)));
            float2 v1 = make_float2(to_tf32(__expf(acc[mt][nt][2] * alpha)),
                                    to_tf32(__expf(acc[mt][nt][3] * alpha)));
            *(float2*)&C[(size_t)row * NT + col] = v0;
            *(float2*)&C[(size_t)(row + 8) * NT + col] = v1;
        }
    }
}

// ================= GEMM 2: O = (E V) / rowsum(E) ==============================
// A = E row-major [NT, NT]; B = V row-major [NT, DV] used directly as [k][n].
// Row sums of E computed in-loop from A fragments by warps with wm==0/64.
#define BV_STRIDE 264   // floats; fragment banks (8*tc+g)%32 all distinct
#define B2_TILE_FLOATS (BK * BV_STRIDE)                      // 8448
#define STAGE2_BYTES ((A_TILE_FLOATS + B2_TILE_FLOATS) * 4)  // 52224
#define SMEM_G2 (NSTG * STAGE2_BYTES)                        // 156672

__global__ __launch_bounds__(256, 1) void gemm_pv_norm(
    const float* __restrict__ A, const float* __restrict__ B, float* __restrict__ C,
    size_t sA, size_t sB, size_t sC)
{
    extern __shared__ char smem[];
    __shared__ float rowinv[BM];
    const int tid = threadIdx.x;
    const int wid = tid >> 5;
    const int lane = tid & 31;
    const int g = lane >> 2;
    const int tc = lane & 3;
    const int K = NT;

    A += (size_t)blockIdx.z * sA;
    B += (size_t)blockIdx.z * sB;
    C += (size_t)blockIdx.z * sC;
    const int bm = blockIdx.y * BM;
    const int bn = blockIdx.x * BN;
    const int wm = (wid & 1) * 64;
    const int wn = (wid >> 1) * 64;

    float acc[4][8][4];
#pragma unroll
    for (int mt = 0; mt < 4; mt++)
#pragma unroll
        for (int nt = 0; nt < 8; nt++)
#pragma unroll
            for (int i = 0; i < 4; i++) acc[mt][nt][i] = 0.f;

    float rs[4][2];
#pragma unroll
    for (int mt = 0; mt < 4; mt++) { rs[mt][0] = 0.f; rs[mt][1] = 0.f; }

    const int nk = K / BK;

#define ISSUE2(it) do {                                                        \
        int _st = (it) % NSTG;                                                 \
        uint32_t _as = smem_u32(smem) + _st * STAGE2_BYTES;                    \
        uint32_t _bs = _as + A_TILE_FLOATS * 4;                                \
        const float* _ga = A + (size_t)bm * K + (size_t)(it) * BK;             \
        const float* _gb = B + (size_t)(it) * BK * DV + bn;                    \
        _Pragma("unroll")                                                      \
        for (int j = 0; j < 4; j++) {                                          \
            int idx = tid + j * 256;                                           \
            int row = idx >> 3, c = (idx & 7) * 4;                             \
            cp_async16(_as + (uint32_t)(row * A_STRIDE + c) * 4,               \
                       _ga + (size_t)row * K + c);                             \
        }                                                                      \
        _Pragma("unroll")                                                      \
        for (int j = 0; j < 8; j++) {                                          \
            int idx = tid + j * 256;                                           \
            int row = idx >> 6, c = (idx & 63) * 4;                            \
            cp_async16(_bs + (uint32_t)(row * BV_STRIDE + c) * 4,              \
                       _gb + (size_t)row * DV + c);                            \
        }                                                                      \
        cp_commit();                                                           \
    } while (0)

    ISSUE2(0);
    ISSUE2(1);

    for (int it = 0; it < nk; it++) {
        if (it < nk - 1) cp_wait<1>(); else cp_wait<0>();
        __syncthreads();
        if (it + 2 < nk) ISSUE2(it + 2);

        const float* As = (const float*)(smem + (it % NSTG) * STAGE2_BYTES);
        const float* Bs = As + A_TILE_FLOATS;

#pragma unroll
        for (int ks = 0; ks < 4; ks++) {
            const int k0 = ks * 8;
            uint32_t a[4][4], b[8][2];
#pragma unroll
            for (int mt = 0; mt < 4; mt++) {
                int m0 = wm + mt * 16 + g;
                a[mt][0] = __float_as_uint(As[m0 * A_STRIDE + k0 + tc]);
                a[mt][1] = __float_as_uint(As[(m0 + 8) * A_STRIDE + k0 + tc]);
                a[mt][2] = __float_as_uint(As[m0 * A_STRIDE + k0 + tc + 4]);
                a[mt][3] = __float_as_uint(As[(m0 + 8) * A_STRIDE + k0 + tc + 4]);
            }
            if (wid < 2) {  // warps wn==0: accumulate exact row sums of E
#pragma unroll
                for (int mt = 0; mt < 4; mt++) {
                    rs[mt][0] += __uint_as_float(a[mt][0]) + __uint_as_float(a[mt][2]);
                    rs[mt][1] += __uint_as_float(a[mt][1]) + __uint_as_float(a[mt][3]);
                }
            }
#pragma unroll
            for (int nt = 0; nt < 8; nt++) {
                int n0 = wn + nt * 8 + g;
                b[nt][0] = __float_as_uint(Bs[(k0 + tc) * BV_STRIDE + n0]);
                b[nt][1] = __float_as_uint(Bs[(k0 + tc + 4) * BV_STRIDE + n0]);
            }
#pragma unroll
            for (int mt = 0; mt < 4; mt++)
#pragma unroll
                for (int nt = 0; nt < 8; nt++)
                    mma_tf32(acc[mt][nt], a[mt], b[nt]);
        }
    }
#undef ISSUE2

    // finish row sums -> rowinv (quad shuffle over tc covers all k mod 8)
    if (wid < 2) {
#pragma unroll
        for (int mt = 0; mt < 4; mt++) {
#pragma unroll
            for (int h2 = 0; h2 < 2; h2++) {
                float s = rs[mt][h2];
                s += __shfl_xor_sync(0xffffffffu, s, 1);
                s += __shfl_xor_sync(0xffffffffu, s, 2);
                if (tc == 0) rowinv[wm + mt * 16 + g + h2 * 8] = 1.f / s;
            }
        }
    }
    __syncthreads();

    // epilogue: normalize and store
#pragma unroll
    for (int mt = 0; mt < 4; mt++) {
        float inv0 = rowinv[wm + mt * 16 + g];
        float inv1 = rowinv[wm + mt * 16 + g + 8];
#pragma unroll
        for (int nt = 0; nt < 8; nt++) {
            int row = bm + wm + mt * 16 + g;
            int col = bn + wn + nt * 8 + 2 * tc;
            float2 v0 = make_float2(acc[mt][nt][0] * inv0, acc[mt][nt][1] * inv0);
            float2 v1 = make_float2(acc[mt][nt][2] * inv1, acc[mt][nt][3] * inv1);
            *(float2*)&C[(size_t)row * DV + col] = v0;
            *(float2*)&C[(size_t)(row + 8) * DV + col] = v1;
        }
    }
}

// ---------------- kernel 1: QKV projection + PReLU + per-head LN ------------
__global__ __launch_bounds__(256) void qkv_kernel(
    const float* __restrict__ x,
    const float* __restrict__ Wq, const float* __restrict__ bq, const float* __restrict__ aq,
    const float* __restrict__ gq, const float* __restrict__ betaq,
    const float* __restrict__ Wk, const float* __restrict__ bk, const float* __restrict__ ak,
    const float* __restrict__ gk, const float* __restrict__ betak,
    const float* __restrict__ Wv, const float* __restrict__ bv, const float* __restrict__ av,
    const float* __restrict__ gv, const float* __restrict__ betav)
{
    __shared__ float sWq[NH * NHC * NC];
    __shared__ float sWk[NH * NHC * NC];
    __shared__ float sWv[NH * NVC * NC];

    int tid = threadIdx.y * 64 + threadIdx.x;
    for (int i = tid; i < NH * NHC * NC; i += 256) { sWq[i] = Wq[i]; sWk[i] = Wk[i]; }
    for (int i = tid; i < NH * NVC * NC; i += 256) { sWv[i] = Wv[i]; }
    __syncthreads();

    int f = threadIdx.x;
    int t = blockIdx.x * 4 + threadIdx.y;
    int b = blockIdx.y;

    const float* xp = x + ((size_t)b * NC * NT + t) * NF + f;

    // hoist: read all 64 channels of x once
    float xr[NC];
#pragma unroll
    for (int c = 0; c < NC; c++) xr[c] = xp[(size_t)c * NT * NF];

    for (int h = 0; h < NH; h++) {
        float q[NHC], k[NHC], v[NVC];
#pragma unroll
        for (int j = 0; j < NHC; j++) { q[j] = 0.f; k[j] = 0.f; }
#pragma unroll
        for (int j = 0; j < NVC; j++) v[j] = 0.f;

#pragma unroll 4
        for (int c0 = 0; c0 < NC; c0 += 4) {
#pragma unroll
            for (int j = 0; j < NHC; j++) {
                float4 w = *(const float4*)&sWq[(h * NHC + j) * NC + c0];
                q[j] += w.x * xr[c0] + w.y * xr[c0 + 1] + w.z * xr[c0 + 2] + w.w * xr[c0 + 3];
            }
#pragma unroll
            for (int j = 0; j < NHC; j++) {
                float4 w = *(const float4*)&sWk[(h * NHC + j) * NC + c0];
                k[j] += w.x * xr[c0] + w.y * xr[c0 + 1] + w.z * xr[c0 + 2] + w.w * xr[c0 + 3];
            }
#pragma unroll
            for (int j = 0; j < NVC; j++) {
                float4 w = *(const float4*)&sWv[(h * NVC + j) * NC + c0];
                v[j] += w.x * xr[c0] + w.y * xr[c0 + 1] + w.z * xr[c0 + 2] + w.w * xr[c0 + 3];
            }
        }
        {
            float a = aq[h], mu = 0.f;
#pragma unroll
            for (int j = 0; j < NHC; j++) {
                float y = q[j] + bq[h * NHC + j];
                y = (y >= 0.f) ? y : a * y; q[j] = y; mu += y;
            }
            mu *= (1.f / NHC);
            float var = 0.f;
#pragma unroll
            for (int j = 0; j < NHC; j++) { float d = q[j] - mu; var += d * d; }
            float r = rsqrtf(var * (1.f / NHC) + EPSV);
#pragma unroll
            for (int j = 0; j < NHC; j++) {
                float o = (q[j] - mu) * r * gq[h * NHC + j] + betaq[h * NHC + j];
                g_Q[((size_t)(h * NB + b) * NT + t) * DQK + j * NF + f] = to_tf32(o);
            }
        }
        {
            float a = ak[h], mu = 0.f;
#pragma unroll
            for (int j = 0; j < NHC; j++) {
                float y = k[j] + bk[h * NHC + j];
                y = (y >= 0.f) ? y : a * y; k[j] = y; mu += y;
            }
            mu *= (1.f / NHC);
            float var = 0.f;
#pragma unroll
            for (int j = 0; j < NHC; j++) { float d = k[j] - mu; var += d * d; }
            float r = rsqrtf(var * (1.f / NHC) + EPSV);
#pragma unroll
            for (int j = 0; j < NHC; j++) {
                float o = (k[j] - mu) * r * gk[h * NHC + j] + betak[h * NHC + j];
                g_K[((size_t)(h * NB + b) * NT + t) * DQK + j * NF + f] = to_tf32(o);
            }
        }
        {
            float a = av[h], mu = 0.f;
#pragma unroll
            for (int j = 0; j < NVC; j++) {
                float y = v[j] + bv[h * NVC + j];
                y = (y >= 0.f) ? y : a * y; v[j] = y; mu += y;
            }
            mu *= (1.f / NVC);
            float var = 0.f;
#pragma unroll
            for (int j = 0; j < NVC; j++) { float d = v[j] - mu; var += d * d; }
            float r = rsqrtf(var * (1.f / NVC) + EPSV);
#pragma unroll
            for (int j = 0; j < NVC; j++) {
                float o = (v[j] - mu) * r * gv[h * NVC + j] + betav[h * NVC + j];
                g_V[((size_t)(h * NB + b) * NT + t) * DV + j * NF + f] = to_tf32(o);
            }
        }
    }
}

// ---------------- output projection + PReLU + LN + residual ------------------
__global__ __launch_bounds__(256) void out_kernel(
    const float* __restrict__ x,
    const float* __restrict__ Wp, const float* __restrict__ bp, const float* __restrict__ ap,
    const float* __restrict__ gp, const float* __restrict__ betap,
    float* __restrict__ out)
{
    __shared__ float sW[NC * NC];
    int tid = threadIdx.y * 64 + threadIdx.x;
    for (int i = tid; i < NC * NC; i += 256) sW[i] = Wp[i];
    __syncthreads();

    int f = threadIdx.x;
    int t = blockIdx.x * 4 + threadIdx.y;
    int b = blockIdx.y;

    float Og[NC];
#pragma unroll
    for (int c = 0; c < NC; c++) {
        int h = c >> 4, vc = c & 15;
        Og[c] = g_O[((size_t)(h * NB + b) * NT + t) * DV + vc * NF + f];
    }

    float a = ap[0];
    float yv[NC];
    float s1 = 0.f, s2 = 0.f;
    for (int o = 0; o < NC; o++) {
        float acc = bp[o];
#pragma unroll
        for (int c0 = 0; c0 < NC; c0 += 4) {
            float4 w = *(const float4*)&sW[o * NC + c0];
            acc += w.x * Og[c0] + w.y * Og[c0 + 1] + w.z * Og[c0 + 2] + w.w * Og[c0 + 3];
        }
        acc = (acc >= 0.f) ? acc : a * acc;
        yv[o] = acc;
        s1 += acc; s2 += acc * acc;
    }
    float mu = s1 * (1.f / NC);
    float var = s2 * (1.f / NC) - mu * mu;
    float r = rsqrtf(var + EPSV);
    for (int o = 0; o < NC; o++) {
        size_t idx = (((size_t)b * NC + o) * NT + t) * NF + f;
        out[idx] = (yv[o] - mu) * r * gp[o] + betap[o] + x[idx];
    }
}

// ---------------- launch ------------------------------------------------------
extern "C" void kernel_launch(void* const* d_in, const int* in_sizes, int n_in,
                              void* d_out, int out_size)
{
    const float* x     = (const float*)d_in[0];
    const float* Wq    = (const float*)d_in[1];
    const float* bq    = (const float*)d_in[2];
    const float* aq    = (const float*)d_in[3];
    const float* gq    = (const float*)d_in[4];
    const float* betaq = (const float*)d_in[5];
    const float* Wk    = (const float*)d_in[6];
    const float* bk    = (const float*)d_in[7];
    const float* ak    = (const float*)d_in[8];
    const float* gk    = (const float*)d_in[9];
    const float* betak = (const float*)d_in[10];
    const float* Wv    = (const float*)d_in[11];
    const float* bv    = (const float*)d_in[12];
    const float* av    = (const float*)d_in[13];
    const float* gv    = (const float*)d_in[14];
    const float* betav = (const float*)d_in[15];
    const float* Wp    = (const float*)d_in[16];
    const float* bp    = (const float*)d_in[17];
    const float* ap    = (const float*)d_in[18];
    const float* gp    = (const float*)d_in[19];
    const float* betap = (const float*)d_in[20];
    float* out = (float*)d_out;

    float *pQ, *pK, *pV, *pE, *pO;
    cudaGetSymbolAddress((void**)&pQ, g_Q);
    cudaGetSymbolAddress((void**)&pK, g_K);
    cudaGetSymbolAddress((void**)&pV, g_V);
    cudaGetSymbolAddress((void**)&pE, g_E);
    cudaGetSymbolAddress((void**)&pO, g_O);

    cudaFuncSetAttribute(gemm_qk_exp, cudaFuncAttributeMaxDynamicSharedMemorySize, SMEM_G1);
    cudaFuncSetAttribute(gemm_pv_norm, cudaFuncAttributeMaxDynamicSharedMemorySize, SMEM_G2);

    // 1) QKV projections (+tf32 rounding)
    qkv_kernel<<<dim3(NT / 4, NB), dim3(64, 4)>>>(
        x, Wq, bq, aq, gq, betaq, Wk, bk, ak, gk, betak, Wv, bv, av, gv, betav);

    // 2) E = exp((1/16) Q K^T)   (softmax numerator, fused epilogue)
    gemm_qk_exp<<<dim3(NT / BN, NT / BM, NHB), 256, SMEM_G1>>>(
        pQ, pK, pE, 0.0625f,
        (size_t)NT * DQK, (size_t)NT * DQK, (size_t)NT * NT);

    // 3) O = (E V) / rowsum(E)   (V loaded directly, in-loop row sums)
    gemm_pv_norm<<<dim3(DV / BN, NT / BM, NHB), 256, SMEM_G2>>>(
        pE, pV, pO,
        (size_t)NT * NT, (size_t)NT * DV, (size_t)NT * DV);

    // 4) output projection + LN + residual
    out_kernel<<<dim3(NT / 4, NB), dim3(64, 4)>>>(
        x, Wp, bp, ap, gp, betap, out);
}